// round 2
// baseline (speedup 1.0000x reference)
#include <cuda_runtime.h>
#include <math.h>

#define Bz 64
#define Tz 512
#define Dz 1024
#define Hz 1024
#define Gz 4096          // 4*H
#define EPSz 1e-5f
#define NCTA 128

typedef unsigned long long ull;

// ---------------- scratch (device globals; no runtime allocation) ----------------
__device__ float g_gih[(size_t)2 * Tz * Bz * Gz];   // LN'd input-side gates, [dir][t][b][4H]
__device__ float g_part[2 * Bz * Gz];               // raw hh gates, [dir][b][4H]
__device__ float g_h[2 * Bz * Hz];                  // hidden state per dir
__device__ float g_c[2 * Bz * Hz];                  // cell state per dir
__device__ unsigned g_cnt = 0;                      // grid barrier count
__device__ unsigned g_gen = 0;                      // grid barrier generation

// packed helpers
__device__ __forceinline__ ull dup2(float v) {
    unsigned u = __float_as_uint(v);
    return (ull)u | ((ull)u << 32);
}
__device__ __forceinline__ void ffma2(ull& acc, ull a, ull b) {
    asm("fma.rn.f32x2 %0, %1, %2, %0;" : "+l"(acc) : "l"(a), "l"(b));
}

// grid-wide barrier (sense-reversing). All NCTA CTAs co-resident (1 wave).
__device__ __forceinline__ void gbar() {
    __syncthreads();
    if (threadIdx.x == 0) {
        unsigned gen = *(volatile unsigned*)&g_gen;
        __threadfence();
        unsigned old = atomicAdd(&g_cnt, 1u);
        if (old == NCTA - 1) {
            atomicExch(&g_cnt, 0u);
            __threadfence();
            atomicAdd(&g_gen, 1u);
        } else {
            while (*(volatile unsigned*)&g_gen == gen) __nanosleep(64);
        }
        __threadfence();
    }
    __syncthreads();
}

// ---------------- input-side GEMM: raw = x @ W_ih^T + b_ih (both dirs) ----------------
// M = T*B = 32768 (row r = t*64+b; bwd reads x at T-1-t), N = 4096, K = 1024.
// 128x128 tile, BK=8, 256 threads, 8x8 microtile via packed f32x2 FMA.
__global__ __launch_bounds__(256)
void gemm_ih_kernel(const float* __restrict__ x,
                    const float* __restrict__ w_f, const float* __restrict__ bias_f,
                    const float* __restrict__ w_b, const float* __restrict__ bias_b) {
    const int dir = blockIdx.z;
    const float* __restrict__ W    = dir ? w_b : w_f;
    const float* __restrict__ bias = dir ? bias_b : bias_f;
    const int row0 = blockIdx.y * 128;
    const int col0 = blockIdx.x * 128;
    const int tid = threadIdx.x;

    __shared__ ull   AsD[8][130];   // A rows, value-duplicated pairs, [k][row]
    __shared__ float Bsf[8][132];   // B, [k][col]; 132 floats = 66 ull per row (16B aligned)

    const int lrow = tid >> 1;          // 0..127
    const int lk   = (tid & 1) * 4;     // 0 or 4
    const int arow = row0 + lrow;
    const int tt = arow >> 6;
    const int bb = arow & 63;
    const int tsrc = dir ? (Tz - 1 - tt) : tt;
    const float* aptr = x + ((size_t)bb * Tz + tsrc) * Dz + lk;
    const float* bptr = W + (size_t)(col0 + lrow) * Dz + lk;

    const int tx = tid & 15;
    const int ty = tid >> 4;

    ull acc[8][4];
#pragma unroll
    for (int i = 0; i < 8; i++)
#pragma unroll
        for (int p = 0; p < 4; p++) acc[i][p] = 0ull;

    float4 av = *(const float4*)(aptr);
    float4 bv = *(const float4*)(bptr);

    for (int k0 = 0; k0 < Dz; k0 += 8) {
        AsD[lk + 0][lrow] = dup2(av.x); AsD[lk + 1][lrow] = dup2(av.y);
        AsD[lk + 2][lrow] = dup2(av.z); AsD[lk + 3][lrow] = dup2(av.w);
        Bsf[lk + 0][lrow] = bv.x; Bsf[lk + 1][lrow] = bv.y;
        Bsf[lk + 2][lrow] = bv.z; Bsf[lk + 3][lrow] = bv.w;
        __syncthreads();
        if (k0 + 8 < Dz) {
            av = *(const float4*)(aptr + k0 + 8);
            bv = *(const float4*)(bptr + k0 + 8);
        }
        const ull* bsp = (const ull*)&Bsf[0][0];   // row kk at kk*66
#pragma unroll
        for (int kk = 0; kk < 8; kk++) {
            ull a[8], b[4];
#pragma unroll
            for (int i = 0; i < 4; i++) {
                a[i]     = AsD[kk][ty * 4 + i];
                a[4 + i] = AsD[kk][64 + ty * 4 + i];
            }
            b[0] = bsp[kk * 66 + tx * 2 + 0];
            b[1] = bsp[kk * 66 + tx * 2 + 1];
            b[2] = bsp[kk * 66 + 32 + tx * 2 + 0];
            b[3] = bsp[kk * 66 + 32 + tx * 2 + 1];
#pragma unroll
            for (int i = 0; i < 8; i++)
#pragma unroll
                for (int p = 0; p < 4; p++)
                    ffma2(acc[i][p], a[i], b[p]);
        }
        __syncthreads();
    }

    float* outbase = g_gih + (size_t)dir * (Tz * Bz) * Gz;
#pragma unroll
    for (int i = 0; i < 8; i++) {
        int r = row0 + ((i < 4) ? (ty * 4 + i) : (64 + ty * 4 + i - 4));
        float* orow = outbase + (size_t)r * Gz;
#pragma unroll
        for (int p = 0; p < 4; p++) {
            int c = col0 + ((p < 2) ? (tx * 4 + p * 2) : (64 + tx * 4 + (p - 2) * 2));
            union { ull u; float2 f; } cv; cv.u = acc[i][p];
            orow[c + 0] = cv.f.x + bias[c + 0];
            orow[c + 1] = cv.f.y + bias[c + 1];
        }
    }
}

// ---------------- LayerNorm (in place) over 4096 gate dim for g_gih ----------------
__global__ void ln_ih_kernel(const float* __restrict__ gain_f, const float* __restrict__ beta_f,
                             const float* __restrict__ gain_b, const float* __restrict__ beta_b) {
    const int row = blockIdx.x;          // dir*32768 + r
    const int dir = row >> 15;
    const float* __restrict__ gain = dir ? gain_b : gain_f;
    const float* __restrict__ beta = dir ? beta_b : beta_f;
    float* p = g_gih + (size_t)row * Gz;
    const int tid = threadIdx.x;

    float4 v[4];
    float sum = 0.f, sq = 0.f;
#pragma unroll
    for (int g = 0; g < 4; g++) {
        v[g] = *(const float4*)(p + g * 1024 + tid * 4);
        sum += v[g].x + v[g].y + v[g].z + v[g].w;
        sq  += v[g].x * v[g].x + v[g].y * v[g].y + v[g].z * v[g].z + v[g].w * v[g].w;
    }
    __shared__ float red[512];
    red[tid] = sum; red[256 + tid] = sq;
    __syncthreads();
    for (int s = 128; s > 0; s >>= 1) {
        if (tid < s) { red[tid] += red[tid + s]; red[256 + tid] += red[256 + tid + s]; }
        __syncthreads();
    }
    float mu = red[0] * (1.f / Gz);
    float var = red[256] * (1.f / Gz) - mu * mu;
    float sc = rsqrtf(var + EPSz);
#pragma unroll
    for (int g = 0; g < 4; g++) {
        int c = g * 1024 + tid * 4;
        float4 gv = *(const float4*)(gain + c);
        float4 bvv = *(const float4*)(beta + c);
        float4 o;
        o.x = (v[g].x - mu) * sc * gv.x + bvv.x;
        o.y = (v[g].y - mu) * sc * gv.y + bvv.y;
        o.z = (v[g].z - mu) * sc * gv.z + bvv.z;
        o.w = (v[g].w - mu) * sc * gv.w + bvv.w;
        *(float4*)(p + c) = o;
    }
}

// ---------------- persistent recurrence: 512 steps, 128 CTAs, grid barriers ----------------
// phase A: CTA (dir, ct) computes raw hh-gates tile [64 batch x 64 cols], K=1024.
// phase B: CTA (dir, b) does LN over 4096 + LSTM pointwise, updates h/c, writes out.
__global__ __launch_bounds__(256)
void lstm_persistent(const float* __restrict__ whh_f, const float* __restrict__ whh_b,
                     const float* __restrict__ bhh_f, const float* __restrict__ ghh_f,
                     const float* __restrict__ behh_f,
                     const float* __restrict__ bhh_b, const float* __restrict__ ghh_b,
                     const float* __restrict__ behh_b,
                     const float* __restrict__ fwd_init, const float* __restrict__ bwd_init,
                     float* __restrict__ out) {
    const int tid = threadIdx.x;
    const int bid = blockIdx.x;

    // init h0/c0
    for (int i = bid * 256 + tid; i < 2 * Bz * Hz; i += NCTA * 256) {
        int dir0 = i >> 16;                 // Bz*Hz = 65536
        int j = i & (Hz - 1);
        const float* init = dir0 ? bwd_init : fwd_init;
        g_h[i] = init[j];
        g_c[i] = init[Hz + j];
    }

    __shared__ ull   AsD[16][66];   // h rows dup-packed, [k][row]
    __shared__ float Bsf[16][66];   // W, [k][col]; 66 floats = 33 ull per row
    __shared__ float red[512];

    const int dir = bid >> 6;
    const int ct  = bid & 63;
    const int col0 = ct * 64;
    const float* __restrict__ W = dir ? whh_b : whh_f;

    const int lrow = tid >> 2;              // 0..63
    const int lk   = (tid & 3) * 4;         // 0,4,8,12
    const float* abase = g_h + (size_t)dir * Bz * Hz + (size_t)lrow * Hz + lk;
    const float* bbase = W + (size_t)(col0 + lrow) * Hz + lk;

    const int tx = tid & 15;
    const int ty = tid >> 4;

    // cell-phase parameters (same (dir, b=ct) decomposition)
    const int cb = ct;
    const float* __restrict__ bhh  = dir ? bhh_b  : bhh_f;
    const float* __restrict__ ghh  = dir ? ghh_b  : ghh_f;
    const float* __restrict__ behh = dir ? behh_b : behh_f;
    float* prow_mine = g_part + ((size_t)dir * Bz + cb) * Gz;
    float* cptr = g_c + ((size_t)dir * Bz + cb) * Hz + tid * 4;
    float* hptr = g_h + ((size_t)dir * Bz + cb) * Hz + tid * 4;
    float* o2   = out + (size_t)Bz * Tz * 2 * Hz + (size_t)cb * (2 * Hz) + dir * Hz + tid * 4;

    gbar();   // h0/c0 visible everywhere

    for (int t = 0; t < Tz; t++) {
        // ================= phase A: raw = h @ Whh^T =================
        ull acc[4][2];
#pragma unroll
        for (int i = 0; i < 4; i++) { acc[i][0] = 0ull; acc[i][1] = 0ull; }

        float4 av = *(const float4*)(abase);
        float4 bv = *(const float4*)(bbase);

        for (int k0 = 0; k0 < Hz; k0 += 16) {
            AsD[lk + 0][lrow] = dup2(av.x); AsD[lk + 1][lrow] = dup2(av.y);
            AsD[lk + 2][lrow] = dup2(av.z); AsD[lk + 3][lrow] = dup2(av.w);
            Bsf[lk + 0][lrow] = bv.x; Bsf[lk + 1][lrow] = bv.y;
            Bsf[lk + 2][lrow] = bv.z; Bsf[lk + 3][lrow] = bv.w;
            __syncthreads();
            if (k0 + 16 < Hz) {
                av = *(const float4*)(abase + k0 + 16);
                bv = *(const float4*)(bbase + k0 + 16);
            }
            const ull* bsp = (const ull*)&Bsf[0][0];   // row kk at kk*33
#pragma unroll
            for (int kk = 0; kk < 16; kk++) {
                ull a0 = AsD[kk][ty * 4 + 0];
                ull a1 = AsD[kk][ty * 4 + 1];
                ull a2 = AsD[kk][ty * 4 + 2];
                ull a3 = AsD[kk][ty * 4 + 3];
                ull b0 = bsp[kk * 33 + tx * 2 + 0];
                ull b1 = bsp[kk * 33 + tx * 2 + 1];
                ffma2(acc[0][0], a0, b0); ffma2(acc[0][1], a0, b1);
                ffma2(acc[1][0], a1, b0); ffma2(acc[1][1], a1, b1);
                ffma2(acc[2][0], a2, b0); ffma2(acc[2][1], a2, b1);
                ffma2(acc[3][0], a3, b0); ffma2(acc[3][1], a3, b1);
            }
            __syncthreads();
        }
#pragma unroll
        for (int i = 0; i < 4; i++) {
            float* orow = g_part + ((size_t)dir * Bz + ty * 4 + i) * Gz + col0 + tx * 4;
            union { ull u; float2 f; } c0, c1;
            c0.u = acc[i][0]; c1.u = acc[i][1];
            *(float4*)orow = make_float4(c0.f.x, c0.f.y, c1.f.x, c1.f.y);
        }

        gbar();   // all raw gate tiles visible

        // ================= phase B: LN + LSTM cell =================
        {
            float4 raw[4];
            float sum = 0.f, sq = 0.f;
#pragma unroll
            for (int g = 0; g < 4; g++) {
                int c = g * 1024 + tid * 4;
                float4 r = *(const float4*)(prow_mine + c);
                float4 bh = *(const float4*)(bhh + c);
                r.x += bh.x; r.y += bh.y; r.z += bh.z; r.w += bh.w;
                raw[g] = r;
                sum += r.x + r.y + r.z + r.w;
                sq  += r.x * r.x + r.y * r.y + r.z * r.z + r.w * r.w;
            }
            red[tid] = sum; red[256 + tid] = sq;
            __syncthreads();
            for (int s = 128; s > 0; s >>= 1) {
                if (tid < s) { red[tid] += red[tid + s]; red[256 + tid] += red[256 + tid + s]; }
                __syncthreads();
            }
            float mu = red[0] * (1.f / Gz);
            float var = red[256] * (1.f / Gz) - mu * mu;
            float sc = rsqrtf(var + EPSz);

            const float* gih = g_gih + ((size_t)dir * Tz * Bz + (size_t)t * Bz + cb) * Gz;
            float gate[4][4];
#pragma unroll
            for (int g = 0; g < 4; g++) {
                int c = g * 1024 + tid * 4;
                float4 gi = *(const float4*)(gih + c);
                float4 gg = *(const float4*)(ghh + c);
                float4 be = *(const float4*)(behh + c);
                gate[g][0] = gi.x + (raw[g].x - mu) * sc * gg.x + be.x;
                gate[g][1] = gi.y + (raw[g].y - mu) * sc * gg.y + be.y;
                gate[g][2] = gi.z + (raw[g].z - mu) * sc * gg.z + be.z;
                gate[g][3] = gi.w + (raw[g].w - mu) * sc * gg.w + be.w;
            }
            float* optr = out + ((size_t)cb * Tz + t) * (2 * Hz) + dir * Hz + tid * 4;
#pragma unroll
            for (int q = 0; q < 4; q++) {
                float iv = 1.f / (1.f + expf(-gate[0][q]));
                float fv = 1.f / (1.f + expf(-gate[1][q]));
                float gv = tanhf(gate[2][q]);
                float ov = 1.f / (1.f + expf(-gate[3][q]));
                float cn = fv * cptr[q] + iv * gv;
                float hn = ov * tanhf(cn);
                cptr[q] = cn;
                hptr[q] = hn;
                optr[q] = hn;
                if (t == Tz - 1) o2[q] = hn;
            }
        }

        gbar();   // new h visible before next step's phase A
    }
}

// ---------------- launch ----------------
extern "C" void kernel_launch(void* const* d_in, const int* in_sizes, int n_in,
                              void* d_out, int out_size) {
    const float* x      = (const float*)d_in[0];
    const float* wih_f  = (const float*)d_in[1];
    const float* whh_f  = (const float*)d_in[2];
    const float* bih_f  = (const float*)d_in[3];
    const float* bhh_f  = (const float*)d_in[4];
    const float* gih_f  = (const float*)d_in[5];
    const float* beih_f = (const float*)d_in[6];
    const float* ghh_f  = (const float*)d_in[7];
    const float* behh_f = (const float*)d_in[8];
    const float* wih_b  = (const float*)d_in[9];
    const float* whh_b  = (const float*)d_in[10];
    const float* bih_b  = (const float*)d_in[11];
    const float* bhh_b  = (const float*)d_in[12];
    const float* gih_b  = (const float*)d_in[13];
    const float* beih_b = (const float*)d_in[14];
    const float* ghh_b  = (const float*)d_in[15];
    const float* behh_b = (const float*)d_in[16];
    const float* fwd_init = (const float*)d_in[17];
    const float* bwd_init = (const float*)d_in[18];
    float* out = (float*)d_out;

    gemm_ih_kernel<<<dim3(32, 256, 2), 256>>>(x, wih_f, bih_f, wih_b, bih_b);
    ln_ih_kernel<<<65536, 256>>>(gih_f, beih_f, gih_b, beih_b);
    lstm_persistent<<<NCTA, 256>>>(whh_f, whh_b,
                                   bhh_f, ghh_f, behh_f,
                                   bhh_b, ghh_b, behh_b,
                                   fwd_init, bwd_init, out);
}